// round 7
// baseline (speedup 1.0000x reference)
#include <cuda_runtime.h>
#include <math.h>

// Problem constants
#define BATCH 16
#define NSEQ  577
#define TOKENS (BATCH*NSEQ)   // 9232
#define DMODEL 768
#define NHEAD 12
#define DH    64
#define MFF   3072

// Scratch (static device globals; no allocation allowed)
__device__ float g_h  [TOKENS * DMODEL];     // LN output (reused)
__device__ float g_qkv[TOKENS * 3 * DMODEL]; // QKV projections
__device__ float g_wa [TOKENS * DMODEL];     // attention output
__device__ float g_x1 [TOKENS * DMODEL];     // after first residual
__device__ float g_act[TOKENS * MFF];        // FC1 + GELU output

// ---------------------------------------------------------------------------
// LayerNorm: one block per token, 256 threads, D=768 (3 elems/thread)
// ---------------------------------------------------------------------------
__global__ __launch_bounds__(256)
void ln_kernel(const float* __restrict__ x, const float* __restrict__ g,
               const float* __restrict__ b, float* __restrict__ y)
{
    const int t = blockIdx.x;
    const float* xr = x + (size_t)t * DMODEL;
    float*       yr = y + (size_t)t * DMODEL;
    const int tid = threadIdx.x;

    float v0 = xr[tid];
    float v1 = xr[tid + 256];
    float v2 = xr[tid + 512];
    float s  = v0 + v1 + v2;
    float sq = v0*v0 + v1*v1 + v2*v2;

    #pragma unroll
    for (int o = 16; o; o >>= 1) {
        s  += __shfl_xor_sync(0xffffffffu, s,  o);
        sq += __shfl_xor_sync(0xffffffffu, sq, o);
    }
    __shared__ float ss[8], sqs[8];
    int w = tid >> 5, l = tid & 31;
    if (l == 0) { ss[w] = s; sqs[w] = sq; }
    __syncthreads();
    s = 0.f; sq = 0.f;
    #pragma unroll
    for (int i = 0; i < 8; i++) { s += ss[i]; sq += sqs[i]; }

    const float inv = 1.0f / (float)DMODEL;
    float mu  = s * inv;
    float var = sq * inv - mu * mu;
    float r   = rsqrtf(var + 1e-5f);

    yr[tid]       = (v0 - mu) * r * g[tid]       + b[tid];
    yr[tid + 256] = (v1 - mu) * r * g[tid + 256] + b[tid + 256];
    yr[tid + 512] = (v2 - mu) * r * g[tid + 512] + b[tid + 512];
}

// ---------------------------------------------------------------------------
// SGEMM: C[M,N] = op(A[M,K] @ W[K,N] + bias [+ resid]).
// 128x128 tile, BK=16, 256 threads, 8x8 per-thread micro tile. Exact fp32.
// OP: 0 = none, 1 = exact GELU, 2 = + residual
// ---------------------------------------------------------------------------
template<int OP>
__global__ __launch_bounds__(256, 2)
void sgemm_kernel(const float* __restrict__ A, const float* __restrict__ W,
                  const float* __restrict__ bias, const float* __restrict__ R,
                  float* __restrict__ C, int M, int N, int K)
{
    __shared__ float As[16][128];   // [k][m]
    __shared__ float Bs[16][128];   // [k][n]

    const int tid = threadIdx.x;
    const int tx = tid & 15;        // col group
    const int ty = tid >> 4;        // row group
    const int m0 = blockIdx.y * 128;
    const int n0 = blockIdx.x * 128;

    const int arow = tid >> 2;          // 0..63
    const int acol = (tid & 3) * 4;     // 0,4,8,12
    const int brow = tid >> 5;          // 0..7
    const int bcol = (tid & 31) * 4;    // 0..124

    float acc[8][8];
    #pragma unroll
    for (int i = 0; i < 8; i++)
        #pragma unroll
        for (int j = 0; j < 8; j++) acc[i][j] = 0.f;

    for (int kt = 0; kt < K; kt += 16) {
        #pragma unroll
        for (int lo = 0; lo < 2; lo++) {
            int r  = arow + lo * 64;
            int gr = m0 + r;
            float4 a = (gr < M) ? *(const float4*)(A + (size_t)gr * K + kt + acol)
                                : make_float4(0.f, 0.f, 0.f, 0.f);
            As[acol + 0][r] = a.x;
            As[acol + 1][r] = a.y;
            As[acol + 2][r] = a.z;
            As[acol + 3][r] = a.w;
        }
        #pragma unroll
        for (int lo = 0; lo < 2; lo++) {
            int r = brow + lo * 8;
            float4 bv = *(const float4*)(W + (size_t)(kt + r) * N + n0 + bcol);
            *(float4*)&Bs[r][bcol] = bv;
        }
        __syncthreads();

        #pragma unroll
        for (int k = 0; k < 16; k++) {
            float ra[8], rb[8];
            *(float4*)(ra)     = *(float4*)&As[k][ty * 8];
            *(float4*)(ra + 4) = *(float4*)&As[k][ty * 8 + 4];
            *(float4*)(rb)     = *(float4*)&Bs[k][tx * 8];
            *(float4*)(rb + 4) = *(float4*)&Bs[k][tx * 8 + 4];
            #pragma unroll
            for (int i = 0; i < 8; i++)
                #pragma unroll
                for (int j = 0; j < 8; j++)
                    acc[i][j] = fmaf(ra[i], rb[j], acc[i][j]);
        }
        __syncthreads();
    }

    // epilogue
    #pragma unroll
    for (int i = 0; i < 8; i++) {
        int gr = m0 + ty * 8 + i;
        if (gr >= M) continue;
        #pragma unroll
        for (int jv = 0; jv < 2; jv++) {
            int gc = n0 + tx * 8 + jv * 4;
            float4 bv = *(const float4*)(bias + gc);
            float v[4];
            v[0] = acc[i][jv*4+0] + bv.x;
            v[1] = acc[i][jv*4+1] + bv.y;
            v[2] = acc[i][jv*4+2] + bv.z;
            v[3] = acc[i][jv*4+3] + bv.w;
            if (OP == 1) {
                #pragma unroll
                for (int j = 0; j < 4; j++)
                    v[j] = 0.5f * v[j] * (1.0f + erff(v[j] * 0.70710678118654752f));
            }
            if (OP == 2) {
                float4 rv = *(const float4*)(R + (size_t)gr * N + gc);
                v[0] += rv.x; v[1] += rv.y; v[2] += rv.z; v[3] += rv.w;
            }
            float4 o = make_float4(v[0], v[1], v[2], v[3]);
            *(float4*)(C + (size_t)gr * N + gc) = o;
        }
    }
}

// ---------------------------------------------------------------------------
// Fused attention (flash-style): one block per (b,h,qtile). 64 q-rows/block,
// loops over 64-row KV tiles with online softmax. 256 threads, 4x4 micro-tile.
// Smem exactly 48KB, all strides 64 (NO row overlap — QSTRIDE=63 was the bug).
//   Q: plain [64][64]
//   K: [64][64] with XOR swizzle  elem e of row r at  r*64 + (e ^ (2*(r>>2)))
//      -> S-loop reads K[4*tx+j][d] land in 16 distinct banks (conflict-free)
//   K buffer reused for P (plain layout) after S phase
//   V: plain [64][64]
// ---------------------------------------------------------------------------
#define Q_OFF 0
#define K_OFF 4096
#define V_OFF 8192
__device__ __forceinline__ int ksw(int row) { return (row & 60) >> 1; }  // = 2*(row>>2)

__global__ __launch_bounds__(256)
void attn_kernel(const float* __restrict__ qkv, float* __restrict__ wa)
{
    __shared__ float sm[12288];   // 49152 bytes exactly
    float* Qs = sm + Q_OFF;
    float* Ks = sm + K_OFF;       // K (swizzled), then P (plain)
    float* Vs = sm + V_OFF;

    const int tid = threadIdx.x;
    const int tx = tid & 15;
    const int ty = tid >> 4;
    const int bh = blockIdx.y;
    const int b = bh / NHEAD, h = bh % NHEAD;
    const int qbase = blockIdx.x * 64;
    const float scale = 0.125f;   // 1/sqrt(64)

    // ---- load Q tile (pre-scaled) ----
    {
        int col = (tid & 15) * 4;
        #pragma unroll
        for (int it = 0; it < 4; it++) {
            int row = (tid >> 4) + it * 16;
            int n = qbase + row;
            float4 q = make_float4(0.f, 0.f, 0.f, 0.f);
            if (n < NSEQ)
                q = *(const float4*)(qkv + (size_t)(b * NSEQ + n) * (3 * DMODEL) + h * DH + col);
            q.x *= scale; q.y *= scale; q.z *= scale; q.w *= scale;
            *(float4*)&Qs[row * 64 + col] = q;
        }
    }

    float O[4][4];
    #pragma unroll
    for (int i = 0; i < 4; i++)
        #pragma unroll
        for (int j = 0; j < 4; j++) O[i][j] = 0.f;
    float m_i[4] = {-1e30f, -1e30f, -1e30f, -1e30f};
    float l_i[4] = {0.f, 0.f, 0.f, 0.f};

    const int NKV = (NSEQ + 63) / 64;   // 10
    for (int t = 0; t < NKV; t++) {
        const int cbase = t * 64;

        // ---- load K (swizzled), V (plain) tiles ----
        {
            int col = (tid & 15) * 4;
            #pragma unroll
            for (int it = 0; it < 4; it++) {
                int row = (tid >> 4) + it * 16;
                int n = cbase + row;
                float4 kv = make_float4(0.f, 0.f, 0.f, 0.f);
                float4 vv = make_float4(0.f, 0.f, 0.f, 0.f);
                if (n < NSEQ) {
                    const float* base = qkv + (size_t)(b * NSEQ + n) * (3 * DMODEL) + h * DH + col;
                    kv = *(const float4*)(base + DMODEL);
                    vv = *(const float4*)(base + 2 * DMODEL);
                }
                int sw = ksw(row);
                Ks[row * 64 + ((col + 0) ^ sw)] = kv.x;
                Ks[row * 64 + ((col + 1) ^ sw)] = kv.y;
                Ks[row * 64 + ((col + 2) ^ sw)] = kv.z;
                Ks[row * 64 + ((col + 3) ^ sw)] = kv.w;
                *(float4*)&Vs[row * 64 + col] = vv;
            }
        }
        __syncthreads();

        // ---- S = (Q*scale) @ K^T ----
        float S[4][4];
        #pragma unroll
        for (int i = 0; i < 4; i++)
            #pragma unroll
            for (int j = 0; j < 4; j++) S[i][j] = 0.f;

        const int swx = tx << 1;   // ksw(4*tx+j) == 2*tx for j in 0..3
        #pragma unroll 8
        for (int d = 0; d < 64; d++) {
            float a[4], bb[4];
            #pragma unroll
            for (int i = 0; i < 4; i++) a[i]  = Qs[(ty * 4 + i) * 64 + d];
            #pragma unroll
            for (int j = 0; j < 4; j++) bb[j] = Ks[(tx * 4 + j) * 64 + (d ^ swx)];
            #pragma unroll
            for (int i = 0; i < 4; i++)
                #pragma unroll
                for (int j = 0; j < 4; j++)
                    S[i][j] = fmaf(a[i], bb[j], S[i][j]);
        }

        // ---- mask invalid kv columns ----
        #pragma unroll
        for (int j = 0; j < 4; j++) {
            if (cbase + tx * 4 + j >= NSEQ) {
                #pragma unroll
                for (int i = 0; i < 4; i++) S[i][j] = -1e30f;
            }
        }

        // ---- online softmax ----
        float rm[4], corr[4], P[4][4], rs[4];
        #pragma unroll
        for (int i = 0; i < 4; i++) {
            rm[i] = fmaxf(fmaxf(S[i][0], S[i][1]), fmaxf(S[i][2], S[i][3]));
            #pragma unroll
            for (int o = 8; o; o >>= 1)
                rm[i] = fmaxf(rm[i], __shfl_xor_sync(0xffffffffu, rm[i], o));
            float mn = fmaxf(m_i[i], rm[i]);
            corr[i] = __expf(m_i[i] - mn);
            m_i[i] = mn;
            rs[i] = 0.f;
            #pragma unroll
            for (int j = 0; j < 4; j++) {
                P[i][j] = __expf(S[i][j] - mn);
                rs[i] += P[i][j];
            }
            #pragma unroll
            for (int o = 8; o; o >>= 1)
                rs[i] += __shfl_xor_sync(0xffffffffu, rs[i], o);
            l_i[i] = l_i[i] * corr[i] + rs[i];
            #pragma unroll
            for (int j = 0; j < 4; j++) O[i][j] *= corr[i];
        }

        __syncthreads();  // everyone done reading Ks

        // ---- store P (plain layout) into Ks buffer ----
        #pragma unroll
        for (int i = 0; i < 4; i++) {
            float4 p = make_float4(P[i][0], P[i][1], P[i][2], P[i][3]);
            *(float4*)&Ks[(ty * 4 + i) * 64 + tx * 4] = p;
        }
        __syncthreads();

        // ---- O += P @ V ----
        #pragma unroll 8
        for (int c = 0; c < 64; c++) {
            float a[4], bb[4];
            #pragma unroll
            for (int i = 0; i < 4; i++) a[i]  = Ks[(ty * 4 + i) * 64 + c];
            #pragma unroll
            for (int j = 0; j < 4; j++) bb[j] = Vs[c * 64 + tx * 4 + j];
            #pragma unroll
            for (int i = 0; i < 4; i++)
                #pragma unroll
                for (int j = 0; j < 4; j++)
                    O[i][j] = fmaf(a[i], bb[j], O[i][j]);
        }
        __syncthreads();  // before next tile overwrites Ks/Vs
    }

    // ---- normalize + write out: wa[b, n, h*64 + d] ----
    #pragma unroll
    for (int i = 0; i < 4; i++) {
        int n = qbase + ty * 4 + i;
        if (n < NSEQ) {
            float inv = 1.0f / l_i[i];
            float4 o = make_float4(O[i][0] * inv, O[i][1] * inv,
                                   O[i][2] * inv, O[i][3] * inv);
            *(float4*)(wa + (size_t)(b * NSEQ + n) * DMODEL + h * DH + tx * 4) = o;
        }
    }
}

// ---------------------------------------------------------------------------
// Launch
// ---------------------------------------------------------------------------
extern "C" void kernel_launch(void* const* d_in, const int* in_sizes, int n_in,
                              void* d_out, int out_size)
{
    const float* x     = (const float*)d_in[0];
    const float* ln1_g = (const float*)d_in[1];
    const float* ln1_b = (const float*)d_in[2];
    const float* w_qkv = (const float*)d_in[3];
    const float* b_qkv = (const float*)d_in[4];
    const float* w_out = (const float*)d_in[5];
    const float* b_out = (const float*)d_in[6];
    const float* ln2_g = (const float*)d_in[7];
    const float* ln2_b = (const float*)d_in[8];
    const float* w_fc1 = (const float*)d_in[9];
    const float* b_fc1 = (const float*)d_in[10];
    const float* w_fc2 = (const float*)d_in[11];
    const float* b_fc2 = (const float*)d_in[12];
    float* out = (float*)d_out;

    float *h, *qkv, *wa, *x1, *act;
    cudaGetSymbolAddress((void**)&h,   g_h);
    cudaGetSymbolAddress((void**)&qkv, g_qkv);
    cudaGetSymbolAddress((void**)&wa,  g_wa);
    cudaGetSymbolAddress((void**)&x1,  g_x1);
    cudaGetSymbolAddress((void**)&act, g_act);

    const int M = TOKENS;
    const int mtiles = (M + 127) / 128;   // 73

    // 1. LN1
    ln_kernel<<<TOKENS, 256>>>(x, ln1_g, ln1_b, h);

    // 2. QKV projection: [T,768] @ [768,2304]
    sgemm_kernel<0><<<dim3(3 * DMODEL / 128, mtiles), 256>>>(
        h, w_qkv, b_qkv, nullptr, qkv, M, 3 * DMODEL, DMODEL);

    // 3. Attention
    attn_kernel<<<dim3((NSEQ + 63) / 64, BATCH * NHEAD), 256>>>(qkv, wa);

    // 4. Output projection + residual: x1 = x + wa @ w_out + b_out
    sgemm_kernel<2><<<dim3(DMODEL / 128, mtiles), 256>>>(
        wa, w_out, b_out, x, x1, M, DMODEL, DMODEL);

    // 5. LN2
    ln_kernel<<<TOKENS, 256>>>(x1, ln2_g, ln2_b, h);

    // 6. FC1 + GELU: [T,768] @ [768,3072]
    sgemm_kernel<1><<<dim3(MFF / 128, mtiles), 256>>>(
        h, w_fc1, b_fc1, nullptr, act, M, MFF, DMODEL);

    // 7. FC2 + residual: out = x1 + act @ w_fc2 + b_fc2
    sgemm_kernel<2><<<dim3(DMODEL / 128, mtiles), 256>>>(
        act, w_fc2, b_fc2, x1, out, M, DMODEL, MFF);
}

// round 8
// speedup vs baseline: 1.9235x; 1.9235x over previous
#include <cuda_runtime.h>
#include <math.h>
#include <stdint.h>

// Problem constants
#define BATCH 16
#define NSEQ  577
#define TOKENS (BATCH*NSEQ)   // 9232
#define DMODEL 768
#define NHEAD 12
#define DH    64
#define MFF   3072

// Scratch (static device globals; no allocation allowed)
__device__ float g_h  [TOKENS * DMODEL];     // LN output (reused)
__device__ float g_qkv[TOKENS * 3 * DMODEL]; // QKV projections
__device__ float g_wa [TOKENS * DMODEL];     // attention output
__device__ float g_x1 [TOKENS * DMODEL];     // after first residual
__device__ float g_act[TOKENS * MFF];        // FC1 + GELU output

// fp32 -> tf32 (round-to-nearest) as a b32 bit pattern for mma.sync
__device__ __forceinline__ uint32_t tf32u(float x) {
    uint32_t u;
    asm("cvt.rna.tf32.f32 %0, %1;" : "=r"(u) : "f"(x));
    return u;
}

// ---------------------------------------------------------------------------
// LayerNorm: one block per token, 256 threads, D=768 (3 elems/thread)
// ---------------------------------------------------------------------------
__global__ __launch_bounds__(256)
void ln_kernel(const float* __restrict__ x, const float* __restrict__ g,
               const float* __restrict__ b, float* __restrict__ y)
{
    const int t = blockIdx.x;
    const float* xr = x + (size_t)t * DMODEL;
    float*       yr = y + (size_t)t * DMODEL;
    const int tid = threadIdx.x;

    float v0 = xr[tid];
    float v1 = xr[tid + 256];
    float v2 = xr[tid + 512];
    float s  = v0 + v1 + v2;
    float sq = v0*v0 + v1*v1 + v2*v2;

    #pragma unroll
    for (int o = 16; o; o >>= 1) {
        s  += __shfl_xor_sync(0xffffffffu, s,  o);
        sq += __shfl_xor_sync(0xffffffffu, sq, o);
    }
    __shared__ float ss[8], sqs[8];
    int w = tid >> 5, l = tid & 31;
    if (l == 0) { ss[w] = s; sqs[w] = sq; }
    __syncthreads();
    s = 0.f; sq = 0.f;
    #pragma unroll
    for (int i = 0; i < 8; i++) { s += ss[i]; sq += sqs[i]; }

    const float inv = 1.0f / (float)DMODEL;
    float mu  = s * inv;
    float var = sq * inv - mu * mu;
    float r   = rsqrtf(var + 1e-5f);

    yr[tid]       = (v0 - mu) * r * g[tid]       + b[tid];
    yr[tid + 256] = (v1 - mu) * r * g[tid + 256] + b[tid + 256];
    yr[tid + 512] = (v2 - mu) * r * g[tid + 512] + b[tid + 512];
}

// ---------------------------------------------------------------------------
// TF32 tensor-core GEMM: C[M,N] = op(A[M,K] @ W[K,N] + bias [+ resid]).
// 128x128 block tile, BK=16, 256 threads = 8 warps (2 m-rows x 4 n-cols),
// warp tile 64x32 via mma.sync.m16n8k8.tf32 (4 m-subtiles x 4 n-subtiles).
// Operands RNA-rounded to tf32 at smem store; fp32 accumulate.
// OP: 0 = none, 1 = exact GELU, 2 = + residual
// ---------------------------------------------------------------------------
#define SPAD 132   // smem row stride (128 + 4) to spread fragment-load banks

template<int OP>
__global__ __launch_bounds__(256, 2)
void tgemm_kernel(const float* __restrict__ A, const float* __restrict__ W,
                  const float* __restrict__ bias, const float* __restrict__ R,
                  float* __restrict__ C, int M, int N, int K)
{
    __shared__ uint32_t As[16][SPAD];   // [k][m] tf32 bits
    __shared__ uint32_t Bs[16][SPAD];   // [k][n] tf32 bits

    const int tid  = threadIdx.x;
    const int warp = tid >> 5;
    const int lane = tid & 31;
    const int g    = lane >> 2;      // groupID 0..7
    const int tg   = lane & 3;       // thread-in-group 0..3
    const int wm   = (warp & 1) * 64;   // warp m offset in block tile
    const int wn   = (warp >> 1) * 32;  // warp n offset
    const int m0 = blockIdx.y * 128;
    const int n0 = blockIdx.x * 128;

    const int arow = tid >> 2;          // 0..63
    const int acol = (tid & 3) * 4;     // 0,4,8,12
    const int brow = tid >> 5;          // 0..7
    const int bcol = (tid & 31) * 4;    // 0..124

    float c[4][4][4];                   // [mi][ni][frag]
    #pragma unroll
    for (int mi = 0; mi < 4; mi++)
        #pragma unroll
        for (int ni = 0; ni < 4; ni++)
            #pragma unroll
            for (int f = 0; f < 4; f++) c[mi][ni][f] = 0.f;

    for (int kt = 0; kt < K; kt += 16) {
        // ---- stage A tile (transposed to [k][m]) ----
        #pragma unroll
        for (int lo = 0; lo < 2; lo++) {
            int r  = arow + lo * 64;
            int gr = m0 + r;
            float4 a = (gr < M) ? *(const float4*)(A + (size_t)gr * K + kt + acol)
                                : make_float4(0.f, 0.f, 0.f, 0.f);
            As[acol + 0][r] = tf32u(a.x);
            As[acol + 1][r] = tf32u(a.y);
            As[acol + 2][r] = tf32u(a.z);
            As[acol + 3][r] = tf32u(a.w);
        }
        // ---- stage B tile [k][n] ----
        #pragma unroll
        for (int lo = 0; lo < 2; lo++) {
            int r = brow + lo * 8;
            float4 bv = *(const float4*)(W + (size_t)(kt + r) * N + n0 + bcol);
            uint4 u;
            u.x = tf32u(bv.x); u.y = tf32u(bv.y);
            u.z = tf32u(bv.z); u.w = tf32u(bv.w);
            *(uint4*)&Bs[r][bcol] = u;
        }
        __syncthreads();

        // ---- two k=8 steps of mma ----
        #pragma unroll
        for (int ks = 0; ks < 16; ks += 8) {
            uint32_t af[4][4];
            #pragma unroll
            for (int mi = 0; mi < 4; mi++) {
                int mb = wm + mi * 16;
                af[mi][0] = As[ks + tg    ][mb + g    ];
                af[mi][1] = As[ks + tg    ][mb + g + 8];
                af[mi][2] = As[ks + tg + 4][mb + g    ];
                af[mi][3] = As[ks + tg + 4][mb + g + 8];
            }
            uint32_t bf[4][2];
            #pragma unroll
            for (int ni = 0; ni < 4; ni++) {
                int nb = wn + ni * 8;
                bf[ni][0] = Bs[ks + tg    ][nb + g];
                bf[ni][1] = Bs[ks + tg + 4][nb + g];
            }
            #pragma unroll
            for (int mi = 0; mi < 4; mi++)
                #pragma unroll
                for (int ni = 0; ni < 4; ni++) {
                    asm volatile(
                        "mma.sync.aligned.m16n8k8.row.col.f32.tf32.tf32.f32 "
                        "{%0,%1,%2,%3}, {%4,%5,%6,%7}, {%8,%9}, {%0,%1,%2,%3};"
                        : "+f"(c[mi][ni][0]), "+f"(c[mi][ni][1]),
                          "+f"(c[mi][ni][2]), "+f"(c[mi][ni][3])
                        : "r"(af[mi][0]), "r"(af[mi][1]),
                          "r"(af[mi][2]), "r"(af[mi][3]),
                          "r"(bf[ni][0]), "r"(bf[ni][1]));
                }
        }
        __syncthreads();
    }

    // ---- epilogue ----
    #pragma unroll
    for (int mi = 0; mi < 4; mi++) {
        #pragma unroll
        for (int ni = 0; ni < 4; ni++) {
            int gc = n0 + wn + ni * 8 + 2 * tg;
            float2 bv = *(const float2*)(bias + gc);
            #pragma unroll
            for (int half = 0; half < 2; half++) {
                int gr = m0 + wm + mi * 16 + g + half * 8;
                if (gr >= M) continue;
                float v0 = c[mi][ni][2*half + 0] + bv.x;
                float v1 = c[mi][ni][2*half + 1] + bv.y;
                if (OP == 1) {
                    v0 = 0.5f * v0 * (1.0f + erff(v0 * 0.70710678118654752f));
                    v1 = 0.5f * v1 * (1.0f + erff(v1 * 0.70710678118654752f));
                }
                if (OP == 2) {
                    float2 rv = *(const float2*)(R + (size_t)gr * N + gc);
                    v0 += rv.x; v1 += rv.y;
                }
                *(float2*)(C + (size_t)gr * N + gc) = make_float2(v0, v1);
            }
        }
    }
}

// ---------------------------------------------------------------------------
// Fused attention (flash-style), exact fp32 — unchanged from round 7 pass.
// ---------------------------------------------------------------------------
#define Q_OFF 0
#define K_OFF 4096
#define V_OFF 8192
__device__ __forceinline__ int ksw(int row) { return (row & 60) >> 1; }  // = 2*(row>>2)

__global__ __launch_bounds__(256)
void attn_kernel(const float* __restrict__ qkv, float* __restrict__ wa)
{
    __shared__ float sm[12288];   // 49152 bytes exactly
    float* Qs = sm + Q_OFF;
    float* Ks = sm + K_OFF;       // K (swizzled), then P (plain)
    float* Vs = sm + V_OFF;

    const int tid = threadIdx.x;
    const int tx = tid & 15;
    const int ty = tid >> 4;
    const int bh = blockIdx.y;
    const int b = bh / NHEAD, h = bh % NHEAD;
    const int qbase = blockIdx.x * 64;
    const float scale = 0.125f;   // 1/sqrt(64)

    // ---- load Q tile (pre-scaled) ----
    {
        int col = (tid & 15) * 4;
        #pragma unroll
        for (int it = 0; it < 4; it++) {
            int row = (tid >> 4) + it * 16;
            int n = qbase + row;
            float4 q = make_float4(0.f, 0.f, 0.f, 0.f);
            if (n < NSEQ)
                q = *(const float4*)(qkv + (size_t)(b * NSEQ + n) * (3 * DMODEL) + h * DH + col);
            q.x *= scale; q.y *= scale; q.z *= scale; q.w *= scale;
            *(float4*)&Qs[row * 64 + col] = q;
        }
    }

    float O[4][4];
    #pragma unroll
    for (int i = 0; i < 4; i++)
        #pragma unroll
        for (int j = 0; j < 4; j++) O[i][j] = 0.f;
    float m_i[4] = {-1e30f, -1e30f, -1e30f, -1e30f};
    float l_i[4] = {0.f, 0.f, 0.f, 0.f};

    const int NKV = (NSEQ + 63) / 64;   // 10
    for (int t = 0; t < NKV; t++) {
        const int cbase = t * 64;

        // ---- load K (swizzled), V (plain) tiles ----
        {
            int col = (tid & 15) * 4;
            #pragma unroll
            for (int it = 0; it < 4; it++) {
                int row = (tid >> 4) + it * 16;
                int n = cbase + row;
                float4 kv = make_float4(0.f, 0.f, 0.f, 0.f);
                float4 vv = make_float4(0.f, 0.f, 0.f, 0.f);
                if (n < NSEQ) {
                    const float* base = qkv + (size_t)(b * NSEQ + n) * (3 * DMODEL) + h * DH + col;
                    kv = *(const float4*)(base + DMODEL);
                    vv = *(const float4*)(base + 2 * DMODEL);
                }
                int sw = ksw(row);
                Ks[row * 64 + ((col + 0) ^ sw)] = kv.x;
                Ks[row * 64 + ((col + 1) ^ sw)] = kv.y;
                Ks[row * 64 + ((col + 2) ^ sw)] = kv.z;
                Ks[row * 64 + ((col + 3) ^ sw)] = kv.w;
                *(float4*)&Vs[row * 64 + col] = vv;
            }
        }
        __syncthreads();

        // ---- S = (Q*scale) @ K^T ----
        float S[4][4];
        #pragma unroll
        for (int i = 0; i < 4; i++)
            #pragma unroll
            for (int j = 0; j < 4; j++) S[i][j] = 0.f;

        const int swx = tx << 1;   // ksw(4*tx+j) == 2*tx for j in 0..3
        #pragma unroll 8
        for (int d = 0; d < 64; d++) {
            float a[4], bb[4];
            #pragma unroll
            for (int i = 0; i < 4; i++) a[i]  = Qs[(ty * 4 + i) * 64 + d];
            #pragma unroll
            for (int j = 0; j < 4; j++) bb[j] = Ks[(tx * 4 + j) * 64 + (d ^ swx)];
            #pragma unroll
            for (int i = 0; i < 4; i++)
                #pragma unroll
                for (int j = 0; j < 4; j++)
                    S[i][j] = fmaf(a[i], bb[j], S[i][j]);
        }

        // ---- mask invalid kv columns ----
        #pragma unroll
        for (int j = 0; j < 4; j++) {
            if (cbase + tx * 4 + j >= NSEQ) {
                #pragma unroll
                for (int i = 0; i < 4; i++) S[i][j] = -1e30f;
            }
        }

        // ---- online softmax ----
        float rm[4], corr[4], P[4][4], rs[4];
        #pragma unroll
        for (int i = 0; i < 4; i++) {
            rm[i] = fmaxf(fmaxf(S[i][0], S[i][1]), fmaxf(S[i][2], S[i][3]));
            #pragma unroll
            for (int o = 8; o; o >>= 1)
                rm[i] = fmaxf(rm[i], __shfl_xor_sync(0xffffffffu, rm[i], o));
            float mn = fmaxf(m_i[i], rm[i]);
            corr[i] = __expf(m_i[i] - mn);
            m_i[i] = mn;
            rs[i] = 0.f;
            #pragma unroll
            for (int j = 0; j < 4; j++) {
                P[i][j] = __expf(S[i][j] - mn);
                rs[i] += P[i][j];
            }
            #pragma unroll
            for (int o = 8; o; o >>= 1)
                rs[i] += __shfl_xor_sync(0xffffffffu, rs[i], o);
            l_i[i] = l_i[i] * corr[i] + rs[i];
            #pragma unroll
            for (int j = 0; j < 4; j++) O[i][j] *= corr[i];
        }

        __syncthreads();  // everyone done reading Ks

        // ---- store P (plain layout) into Ks buffer ----
        #pragma unroll
        for (int i = 0; i < 4; i++) {
            float4 p = make_float4(P[i][0], P[i][1], P[i][2], P[i][3]);
            *(float4*)&Ks[(ty * 4 + i) * 64 + tx * 4] = p;
        }
        __syncthreads();

        // ---- O += P @ V ----
        #pragma unroll 8
        for (int c = 0; c < 64; c++) {
            float a[4], bb[4];
            #pragma unroll
            for (int i = 0; i < 4; i++) a[i]  = Ks[(ty * 4 + i) * 64 + c];
            #pragma unroll
            for (int j = 0; j < 4; j++) bb[j] = Vs[c * 64 + tx * 4 + j];
            #pragma unroll
            for (int i = 0; i < 4; i++)
                #pragma unroll
                for (int j = 0; j < 4; j++)
                    O[i][j] = fmaf(a[i], bb[j], O[i][j]);
        }
        __syncthreads();  // before next tile overwrites Ks/Vs
    }

    // ---- normalize + write out: wa[b, n, h*64 + d] ----
    #pragma unroll
    for (int i = 0; i < 4; i++) {
        int n = qbase + ty * 4 + i;
        if (n < NSEQ) {
            float inv = 1.0f / l_i[i];
            float4 o = make_float4(O[i][0] * inv, O[i][1] * inv,
                                   O[i][2] * inv, O[i][3] * inv);
            *(float4*)(wa + (size_t)(b * NSEQ + n) * DMODEL + h * DH + tx * 4) = o;
        }
    }
}

// ---------------------------------------------------------------------------
// Launch
// ---------------------------------------------------------------------------
extern "C" void kernel_launch(void* const* d_in, const int* in_sizes, int n_in,
                              void* d_out, int out_size)
{
    const float* x     = (const float*)d_in[0];
    const float* ln1_g = (const float*)d_in[1];
    const float* ln1_b = (const float*)d_in[2];
    const float* w_qkv = (const float*)d_in[3];
    const float* b_qkv = (const float*)d_in[4];
    const float* w_out = (const float*)d_in[5];
    const float* b_out = (const float*)d_in[6];
    const float* ln2_g = (const float*)d_in[7];
    const float* ln2_b = (const float*)d_in[8];
    const float* w_fc1 = (const float*)d_in[9];
    const float* b_fc1 = (const float*)d_in[10];
    const float* w_fc2 = (const float*)d_in[11];
    const float* b_fc2 = (const float*)d_in[12];
    float* out = (float*)d_out;

    float *h, *qkv, *wa, *x1, *act;
    cudaGetSymbolAddress((void**)&h,   g_h);
    cudaGetSymbolAddress((void**)&qkv, g_qkv);
    cudaGetSymbolAddress((void**)&wa,  g_wa);
    cudaGetSymbolAddress((void**)&x1,  g_x1);
    cudaGetSymbolAddress((void**)&act, g_act);

    const int M = TOKENS;
    const int mtiles = (M + 127) / 128;   // 73

    // 1. LN1
    ln_kernel<<<TOKENS, 256>>>(x, ln1_g, ln1_b, h);

    // 2. QKV projection: [T,768] @ [768,2304]
    tgemm_kernel<0><<<dim3(3 * DMODEL / 128, mtiles), 256>>>(
        h, w_qkv, b_qkv, nullptr, qkv, M, 3 * DMODEL, DMODEL);

    // 3. Attention
    attn_kernel<<<dim3((NSEQ + 63) / 64, BATCH * NHEAD), 256>>>(qkv, wa);

    // 4. Output projection + residual: x1 = x + wa @ w_out + b_out
    tgemm_kernel<2><<<dim3(DMODEL / 128, mtiles), 256>>>(
        wa, w_out, b_out, x, x1, M, DMODEL, DMODEL);

    // 5. LN2
    ln_kernel<<<TOKENS, 256>>>(x1, ln2_g, ln2_b, h);

    // 6. FC1 + GELU: [T,768] @ [768,3072]
    tgemm_kernel<1><<<dim3(MFF / 128, mtiles), 256>>>(
        h, w_fc1, b_fc1, nullptr, act, M, MFF, DMODEL);

    // 7. FC2 + residual: out = x1 + act @ w_fc2 + b_fc2
    tgemm_kernel<2><<<dim3(DMODEL / 128, mtiles), 256>>>(
        act, w_fc2, b_fc2, x1, out, M, DMODEL, MFF);
}

// round 9
// speedup vs baseline: 3.2433x; 1.6862x over previous
#include <cuda_runtime.h>
#include <math.h>
#include <stdint.h>

// Problem constants
#define BATCH 16
#define NSEQ  577
#define TOKENS (BATCH*NSEQ)   // 9232
#define DMODEL 768
#define NHEAD 12
#define DH    64
#define MFF   3072

// Scratch (static device globals; no allocation allowed)
__device__ float g_h  [TOKENS * DMODEL];     // LN output (reused)
__device__ float g_qkv[TOKENS * 3 * DMODEL]; // QKV projections
__device__ float g_wa [TOKENS * DMODEL];     // attention output
__device__ float g_x1 [TOKENS * DMODEL];     // after first residual
__device__ float g_act[TOKENS * MFF];        // FC1 + GELU output

__device__ __forceinline__ uint32_t smem_u32(const void* p) {
    return (uint32_t)__cvta_generic_to_shared(p);
}
__device__ __forceinline__ void cp16(uint32_t dst, const void* src, int srcbytes) {
    asm volatile("cp.async.cg.shared.global [%0], [%1], 16, %2;"
                 :: "r"(dst), "l"(src), "r"(srcbytes));
}
#define CP_COMMIT() asm volatile("cp.async.commit_group;")
#define CP_WAIT(n)  asm volatile("cp.async.wait_group %0;" :: "n"(n))

// mma.m16n8k8 tf32: raw fp32 bits in registers; HW reads them as tf32
// (truncated mantissa). fp32 accumulate.
__device__ __forceinline__ void mma_tf32(float c[4], const uint32_t a[4], const uint32_t b[2]) {
    asm volatile(
        "mma.sync.aligned.m16n8k8.row.col.f32.tf32.tf32.f32 "
        "{%0,%1,%2,%3}, {%4,%5,%6,%7}, {%8,%9}, {%0,%1,%2,%3};"
        : "+f"(c[0]), "+f"(c[1]), "+f"(c[2]), "+f"(c[3])
        : "r"(a[0]), "r"(a[1]), "r"(a[2]), "r"(a[3]), "r"(b[0]), "r"(b[1]));
}

// ---------------------------------------------------------------------------
// LayerNorm: one block per token, 256 threads, D=768 (3 elems/thread)
// ---------------------------------------------------------------------------
__global__ __launch_bounds__(256)
void ln_kernel(const float* __restrict__ x, const float* __restrict__ g,
               const float* __restrict__ b, float* __restrict__ y)
{
    const int t = blockIdx.x;
    const float* xr = x + (size_t)t * DMODEL;
    float*       yr = y + (size_t)t * DMODEL;
    const int tid = threadIdx.x;

    float v0 = xr[tid];
    float v1 = xr[tid + 256];
    float v2 = xr[tid + 512];
    float s  = v0 + v1 + v2;
    float sq = v0*v0 + v1*v1 + v2*v2;

    #pragma unroll
    for (int o = 16; o; o >>= 1) {
        s  += __shfl_xor_sync(0xffffffffu, s,  o);
        sq += __shfl_xor_sync(0xffffffffu, sq, o);
    }
    __shared__ float ss[8], sqs[8];
    int w = tid >> 5, l = tid & 31;
    if (l == 0) { ss[w] = s; sqs[w] = sq; }
    __syncthreads();
    s = 0.f; sq = 0.f;
    #pragma unroll
    for (int i = 0; i < 8; i++) { s += ss[i]; sq += sqs[i]; }

    const float inv = 1.0f / (float)DMODEL;
    float mu  = s * inv;
    float var = sq * inv - mu * mu;
    float r   = rsqrtf(var + 1e-5f);

    yr[tid]       = (v0 - mu) * r * g[tid]       + b[tid];
    yr[tid + 256] = (v1 - mu) * r * g[tid + 256] + b[tid + 256];
    yr[tid + 512] = (v2 - mu) * r * g[tid + 512] + b[tid + 512];
}

// ---------------------------------------------------------------------------
// TF32 tensor-core GEMM, 2-stage cp.async pipeline.
// C[M,N] = op(A[M,K] @ W[K,N] + bias [+ resid]).
// 128x128 block tile, BK=16, 256 threads = 8 warps (2m x 4n), warp tile 64x32.
// A staged row-major [m][k] stride 20 (conflict-free frag loads, 16B-aligned
// rows); B staged [k][n] stride 132. Raw fp32 -> HW tf32 truncation.
// OP: 0 = none, 1 = exact GELU, 2 = + residual
// ---------------------------------------------------------------------------
struct GemmSmem {
    float As[2][128][20];
    float Bs[2][16][132];
};

__device__ __forceinline__ void gemm_issue(const float* A, const float* W,
                                           GemmSmem& sm, int s, int kt,
                                           int m0, int n0, int M, int N, int K, int tid)
{
    // A tile: 128 rows x 16 cols = 512 float4 chunks
    #pragma unroll
    for (int i = 0; i < 2; i++) {
        int ch  = tid + i * 256;
        int row = ch >> 2;
        int c4  = (ch & 3) * 4;
        const float* src = A + (size_t)(m0 + row) * K + kt + c4;
        int sz = (m0 + row < M) ? 16 : 0;
        cp16(smem_u32(&sm.As[s][row][c4]), src, sz);
    }
    // B tile: 16 rows x 128 cols = 512 float4 chunks
    #pragma unroll
    for (int i = 0; i < 2; i++) {
        int ch  = tid + i * 256;
        int row = ch >> 5;
        int c4  = (ch & 31) * 4;
        const float* src = W + (size_t)(kt + row) * N + n0 + c4;
        cp16(smem_u32(&sm.Bs[s][row][c4]), src, 16);
    }
}

template<int OP>
__global__ __launch_bounds__(256, 2)
void tgemm_kernel(const float* __restrict__ A, const float* __restrict__ W,
                  const float* __restrict__ bias, const float* __restrict__ R,
                  float* __restrict__ C, int M, int N, int K)
{
    __shared__ GemmSmem sm;

    const int tid  = threadIdx.x;
    const int warp = tid >> 5;
    const int lane = tid & 31;
    const int g    = lane >> 2;
    const int tg   = lane & 3;
    const int wm   = (warp & 1) * 64;
    const int wn   = (warp >> 1) * 32;
    const int m0 = blockIdx.y * 128;
    const int n0 = blockIdx.x * 128;

    float c[4][4][4];
    #pragma unroll
    for (int mi = 0; mi < 4; mi++)
        #pragma unroll
        for (int ni = 0; ni < 4; ni++)
            #pragma unroll
            for (int f = 0; f < 4; f++) c[mi][ni][f] = 0.f;

    const int nk = K / 16;
    gemm_issue(A, W, sm, 0, 0, m0, n0, M, N, K, tid);
    CP_COMMIT();

    for (int it = 0; it < nk; it++) {
        const int s = it & 1;
        if (it + 1 < nk) {
            gemm_issue(A, W, sm, s ^ 1, (it + 1) * 16, m0, n0, M, N, K, tid);
            CP_COMMIT();
            CP_WAIT(1);
        } else {
            CP_WAIT(0);
        }
        __syncthreads();

        const uint32_t* Asu = (const uint32_t*)&sm.As[s][0][0];
        const uint32_t* Bsu = (const uint32_t*)&sm.Bs[s][0][0];
        #pragma unroll
        for (int ks = 0; ks < 16; ks += 8) {
            uint32_t af[4][4];
            #pragma unroll
            for (int mi = 0; mi < 4; mi++) {
                int mb = wm + mi * 16;
                af[mi][0] = Asu[(mb + g    ) * 20 + ks + tg    ];
                af[mi][1] = Asu[(mb + g + 8) * 20 + ks + tg    ];
                af[mi][2] = Asu[(mb + g    ) * 20 + ks + tg + 4];
                af[mi][3] = Asu[(mb + g + 8) * 20 + ks + tg + 4];
            }
            uint32_t bf[4][2];
            #pragma unroll
            for (int ni = 0; ni < 4; ni++) {
                int nb = wn + ni * 8;
                bf[ni][0] = Bsu[(ks + tg    ) * 132 + nb + g];
                bf[ni][1] = Bsu[(ks + tg + 4) * 132 + nb + g];
            }
            #pragma unroll
            for (int mi = 0; mi < 4; mi++)
                #pragma unroll
                for (int ni = 0; ni < 4; ni++)
                    mma_tf32(c[mi][ni], af[mi], bf[ni]);
        }
        __syncthreads();
    }

    // ---- epilogue ----
    #pragma unroll
    for (int mi = 0; mi < 4; mi++) {
        #pragma unroll
        for (int ni = 0; ni < 4; ni++) {
            int gc = n0 + wn + ni * 8 + 2 * tg;
            float2 bv = *(const float2*)(bias + gc);
            #pragma unroll
            for (int half = 0; half < 2; half++) {
                int gr = m0 + wm + mi * 16 + g + half * 8;
                if (gr >= M) continue;
                float v0 = c[mi][ni][2*half + 0] + bv.x;
                float v1 = c[mi][ni][2*half + 1] + bv.y;
                if (OP == 1) {
                    v0 = 0.5f * v0 * (1.0f + erff(v0 * 0.70710678118654752f));
                    v1 = 0.5f * v1 * (1.0f + erff(v1 * 0.70710678118654752f));
                }
                if (OP == 2) {
                    float2 rv = *(const float2*)(R + (size_t)gr * N + gc);
                    v0 += rv.x; v1 += rv.y;
                }
                *(float2*)(C + (size_t)gr * N + gc) = make_float2(v0, v1);
            }
        }
    }
}

// ---------------------------------------------------------------------------
// Tensor-core flash attention. One block per (b, h, qtile64). 128 threads =
// 4 warps; warp w owns q-rows [16w, 16w+16). KV tiles of 32 rows.
// S = Q@K^T and O += P@V on mma.m16n8k8.tf32 (raw fp32 = HW truncation).
// Softmax on accumulator fragments (rows g, g+8; quad shfl reduce).
// Smem strides chosen for conflict-free fragment access.
// ---------------------------------------------------------------------------
#define NKV2 ((NSEQ + 31) / 32)   // 19

__global__ __launch_bounds__(128)
void attn_tc_kernel(const float* __restrict__ qkv, float* __restrict__ wa)
{
    __shared__ float Qs[64][68];   // q rows x d   (A operand)
    __shared__ float Ks[32][68];   // kv rows x d  (B operand for S)
    __shared__ float Vs[32][72];   // kv rows x dv (B operand for PV)
    __shared__ float Ps[64][36];   // q rows x kv  (A operand for PV)

    const int tid  = threadIdx.x;
    const int warp = tid >> 5;
    const int lane = tid & 31;
    const int g    = lane >> 2;
    const int tg   = lane & 3;
    const int bh = blockIdx.y;
    const int b = bh / NHEAD, h = bh % NHEAD;
    const int qbase = blockIdx.x * 64;
    const int qr = warp * 16;      // warp's q-row base within tile

    // ---- load Q tile (scaled by 1/8) ----
    #pragma unroll
    for (int i = 0; i < 8; i++) {
        int ch  = tid + i * 128;          // 1024 float4 chunks
        int row = ch >> 4;
        int c4  = (ch & 15) * 4;
        int n = qbase + row;
        float4 q = make_float4(0.f, 0.f, 0.f, 0.f);
        if (n < NSEQ)
            q = *(const float4*)(qkv + (size_t)(b * NSEQ + n) * (3 * DMODEL) + h * DH + c4);
        q.x *= 0.125f; q.y *= 0.125f; q.z *= 0.125f; q.w *= 0.125f;
        *(float4*)&Qs[row][c4] = q;
    }

    float c_o[8][4];
    #pragma unroll
    for (int ni = 0; ni < 8; ni++)
        #pragma unroll
        for (int f = 0; f < 4; f++) c_o[ni][f] = 0.f;
    float m0r = -1e30f, m1r = -1e30f;
    float l0 = 0.f, l1 = 0.f;

    const uint32_t* Qu = (const uint32_t*)&Qs[0][0];
    const uint32_t* Ku = (const uint32_t*)&Ks[0][0];
    const uint32_t* Vu = (const uint32_t*)&Vs[0][0];
    const uint32_t* Pu = (const uint32_t*)&Ps[0][0];

    for (int t = 0; t < NKV2; t++) {
        const int cbase = t * 32;
        __syncthreads();   // prior S (K) + PV (V) reads complete

        // ---- load K, V tiles (32 rows) ----
        #pragma unroll
        for (int i = 0; i < 4; i++) {
            int ch  = tid + i * 128;          // 512 chunks
            int row = ch >> 4;
            int c4  = (ch & 15) * 4;
            int n = cbase + row;
            float4 kv = make_float4(0.f, 0.f, 0.f, 0.f);
            float4 vv = make_float4(0.f, 0.f, 0.f, 0.f);
            if (n < NSEQ) {
                const float* base = qkv + (size_t)(b * NSEQ + n) * (3 * DMODEL) + h * DH + c4;
                kv = *(const float4*)(base + DMODEL);
                vv = *(const float4*)(base + 2 * DMODEL);
            }
            *(float4*)&Ks[row][c4] = kv;
            *(float4*)&Vs[row][c4] = vv;
        }
        __syncthreads();

        // ---- S = Q @ K^T  (warp: 16 x 32) ----
        float c_s[4][4];
        #pragma unroll
        for (int ni = 0; ni < 4; ni++)
            #pragma unroll
            for (int f = 0; f < 4; f++) c_s[ni][f] = 0.f;

        #pragma unroll
        for (int ks = 0; ks < 64; ks += 8) {
            uint32_t af[4];
            af[0] = Qu[(qr + g    ) * 68 + ks + tg    ];
            af[1] = Qu[(qr + g + 8) * 68 + ks + tg    ];
            af[2] = Qu[(qr + g    ) * 68 + ks + tg + 4];
            af[3] = Qu[(qr + g + 8) * 68 + ks + tg + 4];
            #pragma unroll
            for (int ni = 0; ni < 4; ni++) {
                uint32_t bf[2];
                bf[0] = Ku[(ni * 8 + g) * 68 + ks + tg    ];
                bf[1] = Ku[(ni * 8 + g) * 68 + ks + tg + 4];
                mma_tf32(c_s[ni], af, bf);
            }
        }

        // ---- mask invalid kv columns ----
        #pragma unroll
        for (int ni = 0; ni < 4; ni++)
            #pragma unroll
            for (int j = 0; j < 2; j++) {
                if (cbase + ni * 8 + 2 * tg + j >= NSEQ) {
                    c_s[ni][j]     = -1e30f;
                    c_s[ni][j + 2] = -1e30f;
                }
            }

        // ---- online softmax on fragments (rows g and g+8) ----
        float rm0 = -1e30f, rm1 = -1e30f;
        #pragma unroll
        for (int ni = 0; ni < 4; ni++) {
            rm0 = fmaxf(rm0, fmaxf(c_s[ni][0], c_s[ni][1]));
            rm1 = fmaxf(rm1, fmaxf(c_s[ni][2], c_s[ni][3]));
        }
        rm0 = fmaxf(rm0, __shfl_xor_sync(0xffffffffu, rm0, 1));
        rm0 = fmaxf(rm0, __shfl_xor_sync(0xffffffffu, rm0, 2));
        rm1 = fmaxf(rm1, __shfl_xor_sync(0xffffffffu, rm1, 1));
        rm1 = fmaxf(rm1, __shfl_xor_sync(0xffffffffu, rm1, 2));

        float mn0 = fmaxf(m0r, rm0), mn1 = fmaxf(m1r, rm1);
        float corr0 = __expf(m0r - mn0), corr1 = __expf(m1r - mn1);
        m0r = mn0; m1r = mn1;

        float rs0 = 0.f, rs1 = 0.f;
        float p[4][4];
        #pragma unroll
        for (int ni = 0; ni < 4; ni++) {
            p[ni][0] = __expf(c_s[ni][0] - mn0);
            p[ni][1] = __expf(c_s[ni][1] - mn0);
            p[ni][2] = __expf(c_s[ni][2] - mn1);
            p[ni][3] = __expf(c_s[ni][3] - mn1);
            rs0 += p[ni][0] + p[ni][1];
            rs1 += p[ni][2] + p[ni][3];
        }
        rs0 += __shfl_xor_sync(0xffffffffu, rs0, 1);
        rs0 += __shfl_xor_sync(0xffffffffu, rs0, 2);
        rs1 += __shfl_xor_sync(0xffffffffu, rs1, 1);
        rs1 += __shfl_xor_sync(0xffffffffu, rs1, 2);
        l0 = l0 * corr0 + rs0;
        l1 = l1 * corr1 + rs1;

        #pragma unroll
        for (int ni = 0; ni < 8; ni++) {
            c_o[ni][0] *= corr0; c_o[ni][1] *= corr0;
            c_o[ni][2] *= corr1; c_o[ni][3] *= corr1;
        }

        // ---- store P fragments to smem (warp-private rows) ----
        #pragma unroll
        for (int ni = 0; ni < 4; ni++) {
            *(float2*)&Ps[qr + g    ][ni * 8 + 2 * tg] = make_float2(p[ni][0], p[ni][1]);
            *(float2*)&Ps[qr + g + 8][ni * 8 + 2 * tg] = make_float2(p[ni][2], p[ni][3]);
        }
        __syncwarp();

        // ---- O += P @ V  (warp: 16 x 64, k = 32) ----
        #pragma unroll
        for (int ks = 0; ks < 32; ks += 8) {
            uint32_t af[4];
            af[0] = Pu[(qr + g    ) * 36 + ks + tg    ];
            af[1] = Pu[(qr + g + 8) * 36 + ks + tg    ];
            af[2] = Pu[(qr + g    ) * 36 + ks + tg + 4];
            af[3] = Pu[(qr + g + 8) * 36 + ks + tg + 4];
            #pragma unroll
            for (int ni = 0; ni < 8; ni++) {
                uint32_t bf[2];
                bf[0] = Vu[(ks + tg    ) * 72 + ni * 8 + g];
                bf[1] = Vu[(ks + tg + 4) * 72 + ni * 8 + g];
                mma_tf32(c_o[ni], af, bf);
            }
        }
    }

    // ---- normalize + write out ----
    float inv0 = 1.0f / l0, inv1 = 1.0f / l1;
    int row0 = qbase + qr + g;
    int row1 = row0 + 8;
    #pragma unroll
    for (int ni = 0; ni < 8; ni++) {
        int col = h * DH + ni * 8 + 2 * tg;
        if (row0 < NSEQ)
            *(float2*)(wa + (size_t)(b * NSEQ + row0) * DMODEL + col) =
                make_float2(c_o[ni][0] * inv0, c_o[ni][1] * inv0);
        if (row1 < NSEQ)
            *(float2*)(wa + (size_t)(b * NSEQ + row1) * DMODEL + col) =
                make_float2(c_o[ni][2] * inv1, c_o[ni][3] * inv1);
    }
}

// ---------------------------------------------------------------------------
// Launch
// ---------------------------------------------------------------------------
extern "C" void kernel_launch(void* const* d_in, const int* in_sizes, int n_in,
                              void* d_out, int out_size)
{
    const float* x     = (const float*)d_in[0];
    const float* ln1_g = (const float*)d_in[1];
    const float* ln1_b = (const float*)d_in[2];
    const float* w_qkv = (const float*)d_in[3];
    const float* b_qkv = (const float*)d_in[4];
    const float* w_out = (const float*)d_in[5];
    const float* b_out = (const float*)d_in[6];
    const float* ln2_g = (const float*)d_in[7];
    const float* ln2_b = (const float*)d_in[8];
    const float* w_fc1 = (const float*)d_in[9];
    const float* b_fc1 = (const float*)d_in[10];
    const float* w_fc2 = (const float*)d_in[11];
    const float* b_fc2 = (const float*)d_in[12];
    float* out = (float*)d_out;

    float *h, *qkv, *wa, *x1, *act;
    cudaGetSymbolAddress((void**)&h,   g_h);
    cudaGetSymbolAddress((void**)&qkv, g_qkv);
    cudaGetSymbolAddress((void**)&wa,  g_wa);
    cudaGetSymbolAddress((void**)&x1,  g_x1);
    cudaGetSymbolAddress((void**)&act, g_act);

    const int M = TOKENS;
    const int mtiles = (M + 127) / 128;   // 73

    // 1. LN1
    ln_kernel<<<TOKENS, 256>>>(x, ln1_g, ln1_b, h);

    // 2. QKV projection: [T,768] @ [768,2304]
    tgemm_kernel<0><<<dim3(3 * DMODEL / 128, mtiles), 256>>>(
        h, w_qkv, b_qkv, nullptr, qkv, M, 3 * DMODEL, DMODEL);

    // 3. Attention (tensor cores)
    attn_tc_kernel<<<dim3((NSEQ + 63) / 64, BATCH * NHEAD), 128>>>(qkv, wa);

    // 4. Output projection + residual: x1 = x + wa @ w_out + b_out
    tgemm_kernel<2><<<dim3(DMODEL / 128, mtiles), 256>>>(
        wa, w_out, b_out, x, x1, M, DMODEL, DMODEL);

    // 5. LN2
    ln_kernel<<<TOKENS, 256>>>(x1, ln2_g, ln2_b, h);

    // 6. FC1 + GELU: [T,768] @ [768,3072]
    tgemm_kernel<1><<<dim3(MFF / 128, mtiles), 256>>>(
        h, w_fc1, b_fc1, nullptr, act, M, MFF, DMODEL);

    // 7. FC2 + residual: out = x1 + act @ w_fc2 + b_fc2
    tgemm_kernel<2><<<dim3(DMODEL / 128, mtiles), 256>>>(
        act, w_fc2, b_fc2, x1, out, M, DMODEL, MFF);
}

// round 11
// speedup vs baseline: 3.4776x; 1.0722x over previous
#include <cuda_runtime.h>
#include <math.h>
#include <stdint.h>

// Problem constants
#define BATCH 16
#define NSEQ  577
#define TOKENS (BATCH*NSEQ)   // 9232
#define DMODEL 768
#define NHEAD 12
#define DH    64
#define MFF   3072

// Scratch (static device globals; no allocation allowed)
__device__ float g_h  [TOKENS * DMODEL];
__device__ float g_qkv[TOKENS * 3 * DMODEL];
__device__ float g_wa [TOKENS * DMODEL];
__device__ float g_x1 [TOKENS * DMODEL];
__device__ float g_act[TOKENS * MFF];

__device__ __forceinline__ uint32_t smem_u32(const void* p) {
    return (uint32_t)__cvta_generic_to_shared(p);
}
__device__ __forceinline__ void cp16(uint32_t dst, const void* src, int srcbytes) {
    asm volatile("cp.async.cg.shared.global [%0], [%1], 16, %2;"
                 :: "r"(dst), "l"(src), "r"(srcbytes));
}
#define CP_COMMIT() asm volatile("cp.async.commit_group;")
#define CP_WAIT(n)  asm volatile("cp.async.wait_group %0;" :: "n"(n))

__device__ __forceinline__ void mma_tf32(float c[4], const uint32_t a[4], const uint32_t b[2]) {
    asm volatile(
        "mma.sync.aligned.m16n8k8.row.col.f32.tf32.tf32.f32 "
        "{%0,%1,%2,%3}, {%4,%5,%6,%7}, {%8,%9}, {%0,%1,%2,%3};"
        : "+f"(c[0]), "+f"(c[1]), "+f"(c[2]), "+f"(c[3])
        : "r"(a[0]), "r"(a[1]), "r"(a[2]), "r"(a[3]), "r"(b[0]), "r"(b[1]));
}

// ---------------------------------------------------------------------------
// LayerNorm
// ---------------------------------------------------------------------------
__global__ __launch_bounds__(256)
void ln_kernel(const float* __restrict__ x, const float* __restrict__ g,
               const float* __restrict__ b, float* __restrict__ y)
{
    const int t = blockIdx.x;
    const float* xr = x + (size_t)t * DMODEL;
    float*       yr = y + (size_t)t * DMODEL;
    const int tid = threadIdx.x;

    float v0 = xr[tid];
    float v1 = xr[tid + 256];
    float v2 = xr[tid + 512];
    float s  = v0 + v1 + v2;
    float sq = v0*v0 + v1*v1 + v2*v2;

    #pragma unroll
    for (int o = 16; o; o >>= 1) {
        s  += __shfl_xor_sync(0xffffffffu, s,  o);
        sq += __shfl_xor_sync(0xffffffffu, sq, o);
    }
    __shared__ float ss[8], sqs[8];
    int w = tid >> 5, l = tid & 31;
    if (l == 0) { ss[w] = s; sqs[w] = sq; }
    __syncthreads();
    s = 0.f; sq = 0.f;
    #pragma unroll
    for (int i = 0; i < 8; i++) { s += ss[i]; sq += sqs[i]; }

    const float inv = 1.0f / (float)DMODEL;
    float mu  = s * inv;
    float var = sq * inv - mu * mu;
    float r   = rsqrtf(var + 1e-5f);

    yr[tid]       = (v0 - mu) * r * g[tid]       + b[tid];
    yr[tid + 256] = (v1 - mu) * r * g[tid + 256] + b[tid + 256];
    yr[tid + 512] = (v2 - mu) * r * g[tid + 512] + b[tid + 512];
}

// ---------------------------------------------------------------------------
// TF32 GEMM, BK=32, 2-stage cp.async, single sync per iter.
// 128x128 tile, 256 threads = 8 warps (2m x 4n), warp tile 64x32.
// ---------------------------------------------------------------------------
struct GemmSmem {
    float As[2][128][36];   // [m][k], stride 36
    float Bs[2][32][132];   // [k][n], stride 132
};
#define GEMM_SMEM_BYTES sizeof(GemmSmem)

__device__ __forceinline__ void gemm_issue(const float* A, const float* W,
                                           GemmSmem* sm, int s, int kt,
                                           int m0, int n0, int M, int N, int K, int tid)
{
    #pragma unroll
    for (int i = 0; i < 4; i++) {          // A: 128x32 = 1024 chunks
        int ch  = tid + i * 256;
        int row = ch >> 3;
        int c4  = (ch & 7) * 4;
        int gr  = m0 + row;
        int sz  = (gr < M) ? 16 : 0;
        if (gr >= M) gr = M - 1;
        cp16(smem_u32(&sm->As[s][row][c4]), A + (size_t)gr * K + kt + c4, sz);
    }
    #pragma unroll
    for (int i = 0; i < 4; i++) {          // B: 32x128 = 1024 chunks
        int ch  = tid + i * 256;
        int row = ch >> 5;
        int c4  = (ch & 31) * 4;
        cp16(smem_u32(&sm->Bs[s][row][c4]), W + (size_t)(kt + row) * N + n0 + c4, 16);
    }
}

template<int OP>
__global__ __launch_bounds__(256, 2)
void tgemm_kernel(const float* __restrict__ A, const float* __restrict__ W,
                  const float* __restrict__ bias, const float* __restrict__ R,
                  float* __restrict__ C, int M, int N, int K)
{
    extern __shared__ __align__(16) char smem_raw[];
    GemmSmem* sm = (GemmSmem*)smem_raw;

    const int tid  = threadIdx.x;
    const int warp = tid >> 5;
    const int lane = tid & 31;
    const int g    = lane >> 2;
    const int tg   = lane & 3;
    const int wm   = (warp & 1) * 64;
    const int wn   = (warp >> 1) * 32;
    const int m0 = blockIdx.y * 128;
    const int n0 = blockIdx.x * 128;

    float c[4][4][4];
    #pragma unroll
    for (int mi = 0; mi < 4; mi++)
        #pragma unroll
        for (int ni = 0; ni < 4; ni++)
            #pragma unroll
            for (int f = 0; f < 4; f++) c[mi][ni][f] = 0.f;

    const int nk = K / 32;
    gemm_issue(A, W, sm, 0, 0, m0, n0, M, N, K, tid);
    CP_COMMIT();

    for (int it = 0; it < nk; it++) {
        const int s = it & 1;
        CP_WAIT(0);
        __syncthreads();
        if (it + 1 < nk) {
            gemm_issue(A, W, sm, s ^ 1, (it + 1) * 32, m0, n0, M, N, K, tid);
            CP_COMMIT();
        }

        const uint32_t* Asu = (const uint32_t*)&sm->As[s][0][0];
        const uint32_t* Bsu = (const uint32_t*)&sm->Bs[s][0][0];
        #pragma unroll
        for (int ks = 0; ks < 32; ks += 8) {
            uint32_t af[4][4];
            #pragma unroll
            for (int mi = 0; mi < 4; mi++) {
                int mb = wm + mi * 16;
                af[mi][0] = Asu[(mb + g    ) * 36 + ks + tg    ];
                af[mi][1] = Asu[(mb + g + 8) * 36 + ks + tg    ];
                af[mi][2] = Asu[(mb + g    ) * 36 + ks + tg + 4];
                af[mi][3] = Asu[(mb + g + 8) * 36 + ks + tg + 4];
            }
            uint32_t bf[4][2];
            #pragma unroll
            for (int ni = 0; ni < 4; ni++) {
                int nb = wn + ni * 8;
                bf[ni][0] = Bsu[(ks + tg    ) * 132 + nb + g];
                bf[ni][1] = Bsu[(ks + tg + 4) * 132 + nb + g];
            }
            #pragma unroll
            for (int mi = 0; mi < 4; mi++)
                #pragma unroll
                for (int ni = 0; ni < 4; ni++)
                    mma_tf32(c[mi][ni], af[mi], bf[ni]);
        }
        __syncthreads();   // all warps done with slot s before it's re-issued
    }

    // ---- epilogue ----
    #pragma unroll
    for (int mi = 0; mi < 4; mi++) {
        #pragma unroll
        for (int ni = 0; ni < 4; ni++) {
            int gc = n0 + wn + ni * 8 + 2 * tg;
            float2 bv = *(const float2*)(bias + gc);
            #pragma unroll
            for (int half = 0; half < 2; half++) {
                int gr = m0 + wm + mi * 16 + g + half * 8;
                if (gr >= M) continue;
                float v0 = c[mi][ni][2*half + 0] + bv.x;
                float v1 = c[mi][ni][2*half + 1] + bv.y;
                if (OP == 1) {
                    v0 = 0.5f * v0 * (1.0f + erff(v0 * 0.70710678118654752f));
                    v1 = 0.5f * v1 * (1.0f + erff(v1 * 0.70710678118654752f));
                }
                if (OP == 2) {
                    float2 rv = *(const float2*)(R + (size_t)gr * N + gc);
                    v0 += rv.x; v1 += rv.y;
                }
                *(float2*)(C + (size_t)gr * N + gc) = make_float2(v0, v1);
            }
        }
    }
}

// ---------------------------------------------------------------------------
// Tensor-core flash attention. One block per (b, h, qtile128). 256 threads =
// 8 warps; warp w owns q-rows [16w, 16w+16). KV tiles of 32 rows, 2-stage
// cp.async, single sync per iter. Scale applied to S after MMA.
// ---------------------------------------------------------------------------
#define NKV2 ((NSEQ + 31) / 32)   // 19
#define QTILE 128

struct AttnSmem {
    float Qs[QTILE][68];
    float Ks[2][32][68];
    float Vs[2][32][72];
    float Ps[QTILE][36];
};
#define ATTN_SMEM_BYTES sizeof(AttnSmem)

__device__ __forceinline__ void attn_issue_kv(const float* qkv, AttnSmem* sm,
                                              int slot, int cbase, int b, int h, int tid)
{
    #pragma unroll
    for (int i = 0; i < 2; i++) {          // 32 rows x 16 chunks = 512
        int ch  = tid + i * 256;
        int row = ch >> 4;
        int c4  = (ch & 15) * 4;
        int n   = cbase + row;
        int sz  = (n < NSEQ) ? 16 : 0;
        if (n >= NSEQ) n = NSEQ - 1;
        const float* base = qkv + (size_t)(b * NSEQ + n) * (3 * DMODEL) + h * DH + c4;
        cp16(smem_u32(&sm->Ks[slot][row][c4]), base + DMODEL,     sz);
        cp16(smem_u32(&sm->Vs[slot][row][c4]), base + 2 * DMODEL, sz);
    }
}

__global__ __launch_bounds__(256, 2)
void attn_tc_kernel(const float* __restrict__ qkv, float* __restrict__ wa)
{
    extern __shared__ __align__(16) char smem_raw[];
    AttnSmem* sm = (AttnSmem*)smem_raw;

    const int tid  = threadIdx.x;
    const int warp = tid >> 5;
    const int lane = tid & 31;
    const int g    = lane >> 2;
    const int tg   = lane & 3;
    const int bh = blockIdx.y;
    const int b = bh / NHEAD, h = bh % NHEAD;
    const int qbase = blockIdx.x * QTILE;
    const int qr = warp * 16;

    // ---- issue Q (unscaled) + first KV tile together ----
    #pragma unroll
    for (int i = 0; i < 8; i++) {          // 128 rows x 16 chunks = 2048
        int ch  = tid + i * 256;
        int row = ch >> 4;
        int c4  = (ch & 15) * 4;
        int n   = qbase + row;
        int sz  = (n < NSEQ) ? 16 : 0;
        if (n >= NSEQ) n = NSEQ - 1;
        cp16(smem_u32(&sm->Qs[row][c4]),
             qkv + (size_t)(b * NSEQ + n) * (3 * DMODEL) + h * DH + c4, sz);
    }
    attn_issue_kv(qkv, sm, 0, 0, b, h, tid);
    CP_COMMIT();

    float c_o[8][4];
    #pragma unroll
    for (int ni = 0; ni < 8; ni++)
        #pragma unroll
        for (int f = 0; f < 4; f++) c_o[ni][f] = 0.f;
    float m0r = -1e30f, m1r = -1e30f;
    float l0 = 0.f, l1 = 0.f;

    const uint32_t* Qu = (const uint32_t*)&sm->Qs[0][0];
    const uint32_t* Pu = (const uint32_t*)&sm->Ps[0][0];

    for (int t = 0; t < NKV2; t++) {
        const int s = t & 1;
        const int cbase = t * 32;
        CP_WAIT(0);
        __syncthreads();
        if (t + 1 < NKV2) {
            attn_issue_kv(qkv, sm, s ^ 1, (t + 1) * 32, b, h, tid);
            CP_COMMIT();
        }

        const uint32_t* Ku = (const uint32_t*)&sm->Ks[s][0][0];
        const uint32_t* Vu = (const uint32_t*)&sm->Vs[s][0][0];

        // ---- S = Q @ K^T  (warp: 16 x 32) ----
        float c_s[4][4];
        #pragma unroll
        for (int ni = 0; ni < 4; ni++)
            #pragma unroll
            for (int f = 0; f < 4; f++) c_s[ni][f] = 0.f;

        #pragma unroll
        for (int ks = 0; ks < 64; ks += 8) {
            uint32_t af[4];
            af[0] = Qu[(qr + g    ) * 68 + ks + tg    ];
            af[1] = Qu[(qr + g + 8) * 68 + ks + tg    ];
            af[2] = Qu[(qr + g    ) * 68 + ks + tg + 4];
            af[3] = Qu[(qr + g + 8) * 68 + ks + tg + 4];
            #pragma unroll
            for (int ni = 0; ni < 4; ni++) {
                uint32_t bf[2];
                bf[0] = Ku[(ni * 8 + g) * 68 + ks + tg    ];
                bf[1] = Ku[(ni * 8 + g) * 68 + ks + tg + 4];
                mma_tf32(c_s[ni], af, bf);
            }
        }

        // ---- scale then mask ----
        #pragma unroll
        for (int ni = 0; ni < 4; ni++)
            #pragma unroll
            for (int f = 0; f < 4; f++) c_s[ni][f] *= 0.125f;
        #pragma unroll
        for (int ni = 0; ni < 4; ni++)
            #pragma unroll
            for (int j = 0; j < 2; j++) {
                if (cbase + ni * 8 + 2 * tg + j >= NSEQ) {
                    c_s[ni][j]     = -1e30f;
                    c_s[ni][j + 2] = -1e30f;
                }
            }

        // ---- online softmax on fragments ----
        float rm0 = -1e30f, rm1 = -1e30f;
        #pragma unroll
        for (int ni = 0; ni < 4; ni++) {
            rm0 = fmaxf(rm0, fmaxf(c_s[ni][0], c_s[ni][1]));
            rm1 = fmaxf(rm1, fmaxf(c_s[ni][2], c_s[ni][3]));
        }
        rm0 = fmaxf(rm0, __shfl_xor_sync(0xffffffffu, rm0, 1));
        rm0 = fmaxf(rm0, __shfl_xor_sync(0xffffffffu, rm0, 2));
        rm1 = fmaxf(rm1, __shfl_xor_sync(0xffffffffu, rm1, 1));
        rm1 = fmaxf(rm1, __shfl_xor_sync(0xffffffffu, rm1, 2));

        float mn0 = fmaxf(m0r, rm0), mn1 = fmaxf(m1r, rm1);
        float corr0 = __expf(m0r - mn0), corr1 = __expf(m1r - mn1);
        m0r = mn0; m1r = mn1;

        float rs0 = 0.f, rs1 = 0.f;
        float p[4][4];
        #pragma unroll
        for (int ni = 0; ni < 4; ni++) {
            p[ni][0] = __expf(c_s[ni][0] - mn0);
            p[ni][1] = __expf(c_s[ni][1] - mn0);
            p[ni][2] = __expf(c_s[ni][2] - mn1);
            p[ni][3] = __expf(c_s[ni][3] - mn1);
            rs0 += p[ni][0] + p[ni][1];
            rs1 += p[ni][2] + p[ni][3];
        }
        rs0 += __shfl_xor_sync(0xffffffffu, rs0, 1);
        rs0 += __shfl_xor_sync(0xffffffffu, rs0, 2);
        rs1 += __shfl_xor_sync(0xffffffffu, rs1, 1);
        rs1 += __shfl_xor_sync(0xffffffffu, rs1, 2);
        l0 = l0 * corr0 + rs0;
        l1 = l1 * corr1 + rs1;

        #pragma unroll
        for (int ni = 0; ni < 8; ni++) {
            c_o[ni][0] *= corr0; c_o[ni][1] *= corr0;
            c_o[ni][2] *= corr1; c_o[ni][3] *= corr1;
        }

        // ---- store P fragments (warp-private rows) ----
        #pragma unroll
        for (int ni = 0; ni < 4; ni++) {
            *(float2*)&sm->Ps[qr + g    ][ni * 8 + 2 * tg] = make_float2(p[ni][0], p[ni][1]);
            *(float2*)&sm->Ps[qr + g + 8][ni * 8 + 2 * tg] = make_float2(p[ni][2], p[ni][3]);
        }
        __syncwarp();

        // ---- O += P @ V  (warp: 16 x 64, k = 32) ----
        #pragma unroll
        for (int ks = 0; ks < 32; ks += 8) {
            uint32_t af[4];
            af[0] = Pu[(qr + g    ) * 36 + ks + tg    ];
            af[1] = Pu[(qr + g + 8) * 36 + ks + tg    ];
            af[2] = Pu[(qr + g    ) * 36 + ks + tg + 4];
            af[3] = Pu[(qr + g + 8) * 36 + ks + tg + 4];
            #pragma unroll
            for (int ni = 0; ni < 8; ni++) {
                uint32_t bf[2];
                bf[0] = Vu[(ks + tg    ) * 72 + ni * 8 + g];
                bf[1] = Vu[(ks + tg + 4) * 72 + ni * 8 + g];
                mma_tf32(c_o[ni], af, bf);
            }
        }
        __syncthreads();   // done reading slot s before it is re-issued
    }

    // ---- normalize + write out ----
    float inv0 = 1.0f / l0, inv1 = 1.0f / l1;
    int row0 = qbase + qr + g;
    int row1 = row0 + 8;
    #pragma unroll
    for (int ni = 0; ni < 8; ni++) {
        int col = h * DH + ni * 8 + 2 * tg;
        if (row0 < NSEQ)
            *(float2*)(wa + (size_t)(b * NSEQ + row0) * DMODEL + col) =
                make_float2(c_o[ni][0] * inv0, c_o[ni][1] * inv0);
        if (row1 < NSEQ)
            *(float2*)(wa + (size_t)(b * NSEQ + row1) * DMODEL + col) =
                make_float2(c_o[ni][2] * inv1, c_o[ni][3] * inv1);
    }
}

// ---------------------------------------------------------------------------
// Launch
// ---------------------------------------------------------------------------
extern "C" void kernel_launch(void* const* d_in, const int* in_sizes, int n_in,
                              void* d_out, int out_size)
{
    const float* x     = (const float*)d_in[0];
    const float* ln1_g = (const float*)d_in[1];
    const float* ln1_b = (const float*)d_in[2];
    const float* w_qkv = (const float*)d_in[3];
    const float* b_qkv = (const float*)d_in[4];
    const float* w_out = (const float*)d_in[5];
    const float* b_out = (const float*)d_in[6];
    const float* ln2_g = (const float*)d_in[7];
    const float* ln2_b = (const float*)d_in[8];
    const float* w_fc1 = (const float*)d_in[9];
    const float* b_fc1 = (const float*)d_in[10];
    const float* w_fc2 = (const float*)d_in[11];
    const float* b_fc2 = (const float*)d_in[12];
    float* out = (float*)d_out;

    float *h, *qkv, *wa, *x1, *act;
    cudaGetSymbolAddress((void**)&h,   g_h);
    cudaGetSymbolAddress((void**)&qkv, g_qkv);
    cudaGetSymbolAddress((void**)&wa,  g_wa);
    cudaGetSymbolAddress((void**)&x1,  g_x1);
    cudaGetSymbolAddress((void**)&act, g_act);

    cudaFuncSetAttribute(tgemm_kernel<0>, cudaFuncAttributeMaxDynamicSharedMemorySize, GEMM_SMEM_BYTES);
    cudaFuncSetAttribute(tgemm_kernel<1>, cudaFuncAttributeMaxDynamicSharedMemorySize, GEMM_SMEM_BYTES);
    cudaFuncSetAttribute(tgemm_kernel<2>, cudaFuncAttributeMaxDynamicSharedMemorySize, GEMM_SMEM_BYTES);
    cudaFuncSetAttribute(attn_tc_kernel,  cudaFuncAttributeMaxDynamicSharedMemorySize, ATTN_SMEM_BYTES);

    const int M = TOKENS;
    const int mtiles = (M + 127) / 128;   // 73

    // 1. LN1
    ln_kernel<<<TOKENS, 256>>>(x, ln1_g, ln1_b, h);

    // 2. QKV projection
    tgemm_kernel<0><<<dim3(3 * DMODEL / 128, mtiles), 256, GEMM_SMEM_BYTES>>>(
        h, w_qkv, b_qkv, nullptr, qkv, M, 3 * DMODEL, DMODEL);

    // 3. Attention
    attn_tc_kernel<<<dim3((NSEQ + QTILE - 1) / QTILE, BATCH * NHEAD), 256, ATTN_SMEM_BYTES>>>(qkv, wa);

    // 4. Output projection + residual
    tgemm_kernel<2><<<dim3(DMODEL / 128, mtiles), 256, GEMM_SMEM_BYTES>>>(
        wa, w_out, b_out, x, x1, M, DMODEL, DMODEL);

    // 5. LN2
    ln_kernel<<<TOKENS, 256>>>(x1, ln2_g, ln2_b, h);

    // 6. FC1 + GELU
    tgemm_kernel<1><<<dim3(MFF / 128, mtiles), 256, GEMM_SMEM_BYTES>>>(
        h, w_fc1, b_fc1, nullptr, act, M, MFF, DMODEL);

    // 7. FC2 + residual
    tgemm_kernel<2><<<dim3(DMODEL / 128, mtiles), 256, GEMM_SMEM_BYTES>>>(
        act, w_fc2, b_fc2, x1, out, M, DMODEL, MFF);
}